// round 5
// baseline (speedup 1.0000x reference)
#include <cuda_runtime.h>

#define NT 256
#define NBLK 8192                       // (2*256*256*64)/4 / 256
#define SPATIAL (256 * 256 * 64)        // 4194304
#define XSTRIDE (256 * 64)              // 16384
#define YSTRIDE 64

__device__ float g_pb[NBLK];
__device__ float g_pp[NBLK];
__device__ float g_pd[NBLK];
__device__ unsigned int g_cnt = 0;

// corner c encodes (i,j,k): i*4 + j*2 + k.  Row r = i*2+j, z index kc+k.
#define CBX(c) wbx[((((c) >> 2) & 1) * 2) + (((c) >> 1) & 1)][kc + ((c) & 1)]
#define CBY(c) wby[((((c) >> 2) & 1) * 2) + (((c) >> 1) & 1)][kc + ((c) & 1)]
#define CBZ(c) wbz[((((c) >> 2) & 1) * 2) + (((c) >> 1) & 1)][kc + ((c) & 1)]
#define CZZ(c)  wz[((((c) >> 2) & 1) * 2) + (((c) >> 1) & 1)][kc + ((c) & 1)]

__global__ __launch_bounds__(NT) void loss_kernel(
    const float* __restrict__ outp, const float* __restrict__ tgt,
    float* __restrict__ out)
{
    const float EPS = 1e-10f;
    const float DXc = 0.1f, DYc = 0.1f;
    const float SIXTH = 1.0f / 6.0f;

    // vidx bits: z4[0:4) y[4:12) x[12:20) b[20]
    const int vidx = blockIdx.x * NT + threadIdx.x;
    const int z4 = vidx & 15;                       // which float4 along z
    const int y  = (vidx >> 4) & 255;
    const int x  = (vidx >> 12) & 255;
    const int b  = vidx >> 20;
    const int sidx = (vidx & ((1 << 20) - 1)) * 4;  // linear spatial offset

    const float* po = outp + (size_t)b * 3 * SPATIAL + sidx;  // bx_p base
    const float* pt = tgt  + (size_t)b * 4 * SPATIAL + sidx;  // bx_t base

    float sb = 0.f, sp = 0.f, sd = 0.f;

    // ---- pointwise losses: 4 elements via float4 ----
    {
        const float4 vbxp = *(const float4*)(po);
        const float4 vbyp = *(const float4*)(po + SPATIAL);
        const float4 vbzp = *(const float4*)(po + 2 * SPATIAL);
        const float4 vbxt = *(const float4*)(pt);
        const float4 vbyt = *(const float4*)(pt + SPATIAL);
        const float4 vbzt = *(const float4*)(pt + 2 * SPATIAL);
        const float* abxp = (const float*)&vbxp;
        const float* abyp = (const float*)&vbyp;
        const float* abzp = (const float*)&vbzp;
        const float* abxt = (const float*)&vbxt;
        const float* abyt = (const float*)&vbyt;
        const float* abzt = (const float*)&vbzt;
        #pragma unroll
        for (int k = 0; k < 4; k++) {
            const float bxp = abxp[k], byp = abyp[k], bzp = abzp[k];
            const float bxt = abxt[k], byt = abyt[k], bzt = abzt[k];
            const float bxt2 = bxt * bxt, byt2 = byt * byt, bzt2 = bzt * bzt;
            const float t1 = bxp * bxp + byp * byp - bxt2 - byt2;
            sb += t1 * t1 / (bxt2 + byt2 + EPS);
            const float dzv = bzp - bzt;
            const float dz2 = dzv * dzv;
            sb += dz2 * dz2 / (bzt2 + EPS);
            const float cr = bxp * byt - byp * bxt;
            sp += cr * cr / (bxt2 + byt2 + bzt2 + EPS);
        }
    }

    // ---- divergence flux: up to 4 cells (z..z+3), needs z range [z4*4, z4*4+4] ----
    if (x < 255 && y < 255) {
        float wbx[4][5], wby[4][5], wbz[4][5], wz[4][5];
        const float* pz = pt + 3 * SPATIAL;
        const bool tail = (z4 < 15);     // scalar z+4 element exists & is needed
        #pragma unroll
        for (int i = 0; i < 2; i++) {
            #pragma unroll
            for (int j = 0; j < 2; j++) {
                const int r = i * 2 + j;
                const int off = i * XSTRIDE + j * YSTRIDE;
                float4 v;
                v = *(const float4*)(po + off);
                wbx[r][0] = v.x; wbx[r][1] = v.y; wbx[r][2] = v.z; wbx[r][3] = v.w;
                wbx[r][4] = tail ? po[off + 4] : 0.f;
                v = *(const float4*)(po + SPATIAL + off);
                wby[r][0] = v.x; wby[r][1] = v.y; wby[r][2] = v.z; wby[r][3] = v.w;
                wby[r][4] = tail ? po[SPATIAL + off + 4] : 0.f;
                v = *(const float4*)(po + 2 * SPATIAL + off);
                wbz[r][0] = v.x; wbz[r][1] = v.y; wbz[r][2] = v.z; wbz[r][3] = v.w;
                wbz[r][4] = tail ? po[2 * SPATIAL + off + 4] : 0.f;
                v = *(const float4*)(pz + off);
                wz[r][0] = v.x; wz[r][1] = v.y; wz[r][2] = v.z; wz[r][3] = v.w;
                wz[r][4] = tail ? pz[off + 4] : 0.f;
            }
        }

        const int kmax = tail ? 4 : 3;   // cell z=63 invalid
        #pragma unroll
        for (int kc = 0; kc < 4; kc++) {
            if (kc < kmax) {
                float num =
                      0.25f * (CBX(4) + CBX(6) + CBX(5) + CBX(7)) * DYc * 0.5f * (CZZ(5) - CZZ(4) + CZZ(7) - CZZ(6))
                    - 0.25f * (CBX(0) + CBX(2) + CBX(1) + CBX(3)) * DYc * 0.5f * (CZZ(1) - CZZ(0) + CZZ(3) - CZZ(2))
                    + 0.25f * (CBY(2) + CBY(6) + CBY(3) + CBY(7)) * DXc * 0.5f * (CZZ(3) - CZZ(2) + CZZ(7) - CZZ(6))
                    - 0.25f * (CBY(0) + CBY(4) + CBY(1) + CBY(5)) * DXc * 0.5f * (CZZ(1) - CZZ(0) + CZZ(5) - CZZ(4))
                    + 0.25f * (CBZ(1) + CBZ(3) + CBZ(5) + CBZ(7)) * DXc * DYc
                    - 0.25f * (CBZ(0) + CBZ(2) + CBZ(4) + CBZ(6)) * DXc * DYc
                    + (CBX(1) + CBX(5) + CBX(7)) * DYc * (CZZ(1) - CZZ(5)) * SIXTH
                    + (CBX(3) + CBX(7) + CBX(5)) * DYc * (CZZ(3) - CZZ(7)) * SIXTH
                    + (CBY(5) + CBY(7) + CBY(3)) * DXc * (CZZ(5) - CZZ(7)) * SIXTH
                    + (CBY(1) + CBY(3) + CBY(7)) * DXc * (CZZ(1) - CZZ(3)) * SIXTH
                    - (CBX(0) + CBX(4) + CBX(6)) * DYc * (CZZ(0) - CZZ(4)) * SIXTH
                    - (CBX(2) + CBX(6) + CBX(4)) * DYc * (CZZ(2) - CZZ(6)) * SIXTH
                    - (CBY(4) + CBY(6) + CBY(2)) * DXc * (CZZ(4) - CZZ(6)) * SIXTH
                    - (CBY(0) + CBY(2) + CBY(6)) * DXc * (CZZ(0) - CZZ(2)) * SIXTH;

                const float bxc = 0.125f * (CBX(0) + CBX(1) + CBX(2) + CBX(3) + CBX(4) + CBX(5) + CBX(6) + CBX(7));
                const float byc = 0.125f * (CBY(0) + CBY(1) + CBY(2) + CBY(3) + CBY(4) + CBY(5) + CBY(6) + CBY(7));
                const float bzc = 0.125f * (CBZ(0) + CBZ(1) + CBZ(2) + CBZ(3) + CBZ(4) + CBZ(5) + CBZ(6) + CBZ(7));
                const float den = bxc * bxc + byc * byc + bzc * bzc + EPS;
                sd += num * num / den;
            }
        }
    }

    // ---- deterministic block reduction ----
    __shared__ float shb[NT], shp[NT], shd[NT];
    shb[threadIdx.x] = sb;
    shp[threadIdx.x] = sp;
    shd[threadIdx.x] = sd;
    __syncthreads();
    for (int s = NT / 2; s > 0; s >>= 1) {
        if (threadIdx.x < s) {
            shb[threadIdx.x] += shb[threadIdx.x + s];
            shp[threadIdx.x] += shp[threadIdx.x + s];
            shd[threadIdx.x] += shd[threadIdx.x + s];
        }
        __syncthreads();
    }

    __shared__ bool isLast;
    if (threadIdx.x == 0) {
        g_pb[blockIdx.x] = shb[0];
        g_pp[blockIdx.x] = shp[0];
        g_pd[blockIdx.x] = shd[0];
        __threadfence();
        isLast = (atomicAdd(&g_cnt, 1u) == NBLK - 1);
    }
    __syncthreads();

    // ---- last block: final deterministic reduce in double ----
    if (isLast) {
        __threadfence();
        __shared__ double rb[NT], rp[NT], rd[NT];
        double db = 0.0, dp = 0.0, dd = 0.0;
        for (int i = threadIdx.x; i < NBLK; i += NT) {
            db += (double)__ldcg(&g_pb[i]);
            dp += (double)__ldcg(&g_pp[i]);
            dd += (double)__ldcg(&g_pd[i]);
        }
        rb[threadIdx.x] = db; rp[threadIdx.x] = dp; rd[threadIdx.x] = dd;
        __syncthreads();
        for (int s = NT / 2; s > 0; s >>= 1) {
            if (threadIdx.x < s) {
                rb[threadIdx.x] += rb[threadIdx.x + s];
                rp[threadIdx.x] += rp[threadIdx.x + s];
                rd[threadIdx.x] += rd[threadIdx.x + s];
            }
            __syncthreads();
        }
        if (threadIdx.x == 0) {
            const double N = 8388608.0;            // 2*256*256*64
            const double M = 8193150.0;            // 2*255*255*63
            const double loss_b   = rb[0] / N;
            const double loss_p   = rp[0] / N;
            const double loss_div = rd[0] / M * 1.0e4;   // / DX^2 / DY^2
            out[0] = (float)(1000.0 * loss_b + 1000.0 * loss_p);
            out[1] = (float)(100.0 * loss_div);
            g_cnt = 0;                              // reset for graph replay
        }
    }
}

extern "C" void kernel_launch(void* const* d_in, const int* in_sizes, int n_in,
                              void* d_out, int out_size)
{
    const float* outputs = (const float*)d_in[0];
    const float* targets = (const float*)d_in[1];
    float* out = (float*)d_out;
    loss_kernel<<<NBLK, NT>>>(outputs, targets, out);
}

// round 6
// speedup vs baseline: 1.3376x; 1.3376x over previous
#include <cuda_runtime.h>

#define NT 256
#define NB 2048
#define SPATIAL (256 * 256 * 64)   // 4194304
#define NTOT    (2 * SPATIAL)      // 8388608
#define XS (256 * 64)              // x stride
#define YS 64                      // y stride

__device__ float g_pb[NB];
__device__ float g_pp[NB];
__device__ float g_pd[NB];
__device__ unsigned int g_cnt = 0;

__global__ __launch_bounds__(NT, 5) void loss_kernel(
    const float* __restrict__ outp, const float* __restrict__ tgt,
    float* __restrict__ out)
{
    const float EPS = 1e-10f;
    const float C8  = 0.0125f;        // 0.125 * DX (= 0.125 * DY)
    const float C6  = 0.1f / 6.0f;    // DX/6 = DY/6
    const float CZ  = 0.0025f;        // 0.25 * DX * DY

    float sb = 0.f, sp = 0.f, sd = 0.f;

    for (int idx = blockIdx.x * NT + threadIdx.x; idx < NTOT; idx += NB * NT) {
        const int b    = idx >> 22;
        const int sidx = idx & (SPATIAL - 1);
        const int z    = sidx & 63;
        const int y    = (sidx >> 6) & 255;
        const int x    = sidx >> 14;

        const float* po = outp + (size_t)b * 3 * SPATIAL + sidx;   // bx_p
        const float* pt = tgt  + (size_t)b * 4 * SPATIAL + sidx;   // bx_t

        // ---- pointwise losses ----
        {
            const float bxp = po[0], byp = po[SPATIAL], bzp = po[2 * SPATIAL];
            const float bxt = pt[0], byt = pt[SPATIAL], bzt = pt[2 * SPATIAL];
            const float bxt2 = bxt * bxt, byt2 = byt * byt, bzt2 = bzt * bzt;
            const float t1 = bxp * bxp + byp * byp - bxt2 - byt2;
            sb += t1 * t1 / (bxt2 + byt2 + EPS);
            const float dv = bzp - bzt;
            const float dv2 = dv * dv;
            sb += dv2 * dv2 / (bzt2 + EPS);
            const float cr = bxp * byt - byp * bxt;
            sp += cr * cr / (bxt2 + byt2 + bzt2 + EPS);
        }

        // ---- divergence flux loss, coefficient-streamed ----
        if (x < 255 && y < 255 && z < 63) {
            // corner c = (i,j,k) -> i*4 + j*2 + k; offset i*XS + j*YS + k
            const float* pz = pt + 3 * SPATIAL;
            const float z0 = pz[0],       z1 = pz[1];
            const float z2 = pz[YS],      z3 = pz[YS + 1];
            const float z4 = pz[XS],      z5 = pz[XS + 1];
            const float z6 = pz[XS + YS], z7 = pz[XS + YS + 1];

            // bx coefficients
            const float q1 =  C8 * (z5 - z4 + z7 - z6);
            const float q2 = -C8 * (z1 - z0 + z3 - z2);
            const float r1 =  C6 * (z1 - z5);
            const float r2 =  C6 * (z3 - z7);
            const float r3 =  C6 * (z4 - z0);
            const float r4 =  C6 * (z6 - z2);
            // by coefficients
            const float s1 =  C8 * (z3 - z2 + z7 - z6);
            const float s2 = -C8 * (z1 - z0 + z5 - z4);
            const float u1 =  C6 * (z5 - z7);
            const float u2 =  C6 * (z1 - z3);
            const float u3 =  C6 * (z6 - z4);
            const float u4 =  C6 * (z2 - z0);

            float num, bxc, byc, bzc;
            {   // bx batch
                const float c0 = po[0],       c1 = po[1];
                const float c2 = po[YS],      c3 = po[YS + 1];
                const float c4 = po[XS],      c5 = po[XS + 1];
                const float c6 = po[XS + YS], c7 = po[XS + YS + 1];
                num = c0 * (q2 + r3) + c1 * (q2 + r1)
                    + c2 * (q2 + r4) + c3 * (q2 + r2)
                    + (c4 + c6) * (q1 + (r3 + r4))
                    + (c5 + c7) * (q1 + (r1 + r2));
                bxc = ((c0 + c1) + (c2 + c3)) + ((c4 + c5) + (c6 + c7));
            }
            {   // by batch
                const float* py = po + SPATIAL;
                const float c0 = py[0],       c1 = py[1];
                const float c2 = py[YS],      c3 = py[YS + 1];
                const float c4 = py[XS],      c5 = py[XS + 1];
                const float c6 = py[XS + YS], c7 = py[XS + YS + 1];
                num += c0 * (s2 + u4) + c1 * (s2 + u2)
                     + c4 * (s2 + u3) + c5 * (s2 + u1)
                     + (c2 + c6) * (s1 + (u3 + u4))
                     + (c3 + c7) * (s1 + (u1 + u2));
                byc = ((c0 + c1) + (c2 + c3)) + ((c4 + c5) + (c6 + c7));
            }
            {   // bz batch
                const float* pb = po + 2 * SPATIAL;
                const float c0 = pb[0],       c1 = pb[1];
                const float c2 = pb[YS],      c3 = pb[YS + 1];
                const float c4 = pb[XS],      c5 = pb[XS + 1];
                const float c6 = pb[XS + YS], c7 = pb[XS + YS + 1];
                num += CZ * (((c1 + c3) + (c5 + c7)) - ((c0 + c2) + (c4 + c6)));
                bzc = ((c0 + c1) + (c2 + c3)) + ((c4 + c5) + (c6 + c7));
            }
            bxc *= 0.125f; byc *= 0.125f; bzc *= 0.125f;
            const float den = bxc * bxc + byc * byc + bzc * bzc + EPS;
            sd += num * num / den;
        }
    }

    // ---- deterministic block reduction ----
    __shared__ float shb[NT], shp[NT], shd[NT];
    shb[threadIdx.x] = sb;
    shp[threadIdx.x] = sp;
    shd[threadIdx.x] = sd;
    __syncthreads();
    for (int s = NT / 2; s > 0; s >>= 1) {
        if (threadIdx.x < s) {
            shb[threadIdx.x] += shb[threadIdx.x + s];
            shp[threadIdx.x] += shp[threadIdx.x + s];
            shd[threadIdx.x] += shd[threadIdx.x + s];
        }
        __syncthreads();
    }

    __shared__ bool isLast;
    if (threadIdx.x == 0) {
        g_pb[blockIdx.x] = shb[0];
        g_pp[blockIdx.x] = shp[0];
        g_pd[blockIdx.x] = shd[0];
        __threadfence();
        isLast = (atomicAdd(&g_cnt, 1u) == NB - 1);
    }
    __syncthreads();

    // ---- last block: final deterministic reduce in double ----
    if (isLast) {
        __threadfence();
        __shared__ double rb[NT], rp[NT], rd[NT];
        double db = 0.0, dp = 0.0, dd = 0.0;
        for (int i = threadIdx.x; i < NB; i += NT) {
            db += (double)__ldcg(&g_pb[i]);
            dp += (double)__ldcg(&g_pp[i]);
            dd += (double)__ldcg(&g_pd[i]);
        }
        rb[threadIdx.x] = db; rp[threadIdx.x] = dp; rd[threadIdx.x] = dd;
        __syncthreads();
        for (int s = NT / 2; s > 0; s >>= 1) {
            if (threadIdx.x < s) {
                rb[threadIdx.x] += rb[threadIdx.x + s];
                rp[threadIdx.x] += rp[threadIdx.x + s];
                rd[threadIdx.x] += rd[threadIdx.x + s];
            }
            __syncthreads();
        }
        if (threadIdx.x == 0) {
            const double N = 8388608.0;            // 2*256*256*64
            const double M = 8193150.0;            // 2*255*255*63
            const double loss_b   = rb[0] / N;
            const double loss_p   = rp[0] / N;
            const double loss_div = rd[0] / M * 1.0e4;   // / DX^2 / DY^2
            out[0] = (float)(1000.0 * loss_b + 1000.0 * loss_p);
            out[1] = (float)(100.0 * loss_div);
            g_cnt = 0;                              // reset for graph replay
        }
    }
}

extern "C" void kernel_launch(void* const* d_in, const int* in_sizes, int n_in,
                              void* d_out, int out_size)
{
    const float* outputs = (const float*)d_in[0];
    const float* targets = (const float*)d_in[1];
    float* out = (float*)d_out;
    loss_kernel<<<NB, NT>>>(outputs, targets, out);
}